// round 12
// baseline (speedup 1.0000x reference)
#include <cuda_runtime.h>
#include <cstdint>
#include <cstddef>

// ---------------------------------------------------------------------------
// SNN, fp32-faithful, PASSING association (round 9): per output, fp32 FMA
// chain ascending k; K panels [0,512),[512,1024); panel sums combined with
// one rounded add. Schedule-only changes this round:
//  * accumulators packed along n -> B packed pairs load DIRECTLY from smem
//    (consecutive floats), only 4 A-dup MOVs per kk (ALU pipe)
//  * crossbar/SM/kk = 96 cyc < 128 cyc FMA demand -> FMA-bound
//  * KTILE=32 (32 syncs), panel-1 partials stashed to smem (no spills in any
//    MODE), dynamic smem 130KB, 512 threads, tile 128x128
// ---------------------------------------------------------------------------

#define NB 16384
#define NH 1024
#define NSTEPS 25
#define NO 10

#define KTILE 32
#define SMP 132        // smem row pitch (floats)
#define SA_BYTES  (2 * KTILE * SMP * 4)
#define SB_BYTES  (2 * KTILE * SMP * 4)
#define STASH_BYTES (16 * 512 * 8)
#define SMEM_TOTAL (SA_BYTES + SB_BYTES + STASH_BYTES)

// ----------------------------- device scratch ------------------------------
__device__ __align__(16) float g_spk1a[NB * NH];
__device__ __align__(16) float g_spk1b[NB * NH];
__device__ __align__(16) float g_spk2a[NB * NH];
__device__ __align__(16) float g_spk2b[NB * NH];
__device__ __align__(16) float g_mem1[NB * NH];
__device__ __align__(16) float g_mem2[NB * NH];
__device__ __align__(16) float g_cur1[NB * NH];
__device__ __align__(16) float g_cur2[NB * NH];
__device__ __align__(16) float g_ssum[NB * NH];

// --------------------------- f32x2 packed helpers ---------------------------
__device__ __forceinline__ uint64_t dup2(float x) {
    uint64_t d;
    asm("mov.b64 %0, {%1, %2};" : "=l"(d) : "f"(x), "f"(x));
    return d;
}
__device__ __forceinline__ uint64_t fma2(uint64_t a, uint64_t b, uint64_t c) {
    uint64_t d;
    asm("fma.rn.f32x2 %0, %1, %2, %3;" : "=l"(d) : "l"(a), "l"(b), "l"(c));
    return d;
}
__device__ __forceinline__ uint64_t add2(uint64_t a, uint64_t b) {
    uint64_t d;
    asm("add.rn.f32x2 %0, %1, %2;" : "=l"(d) : "l"(a), "l"(b));
    return d;
}
__device__ __forceinline__ float2 unpk2(uint64_t v) {
    float lo, hi;
    asm("mov.b64 {%0, %1}, %2;" : "=f"(lo), "=f"(hi) : "l"(v));
    return make_float2(lo, hi);
}

// ------------------------------- prep kernels ------------------------------
__global__ void init_state_kernel() {
    size_t i = (size_t)blockIdx.x * blockDim.x + threadIdx.x;
    g_mem1[i] = 0.f;
    g_mem2[i] = 0.f;
    g_ssum[i] = 0.f;
    g_spk1a[i] = 0.f;
    g_spk2a[i] = 0.f;
}

__global__ void div25_kernel(float* __restrict__ s) {
    size_t i = (size_t)blockIdx.x * blockDim.x + threadIdx.x;
    s[i] = __fdiv_rn(s[i], 25.0f);
}

// ------------------------------- GEMM kernel -------------------------------
// C[m,n] = sum_k A[m,k]*B[n,k]: panels [0,512),[512,1024), serial ascending
// k within panel, one rounded add to combine (EXACTLY as passing R9).
// 512 threads: warp w -> cols [w*8, w*8+8); lane -> rows [lane*4, lane*4+4).
// acc2[i][j2]: row lm+i, cols (nw0+2*j2, nw0+2*j2+1) packed.

// MODE 0: outC = tot + biasA[n]
// MODE 1: mem = 0.5*mem + cur + tot + biasA - reset; spike; [DOSUM] ssum += s
template <int MODE, int DOSUM>
__global__ void __launch_bounds__(512, 1)
f32gemm_kernel(const float* __restrict__ Ag, const float* __restrict__ Bg,
               const float* __restrict__ biasA,
               float* __restrict__ memBuf, const float* __restrict__ curBuf,
               float* __restrict__ spkOut,
               float* __restrict__ ssum, float* __restrict__ outC) {
    extern __shared__ __align__(16) char dsmem[];
    float* sA = (float*)dsmem;                     // [2][KTILE][SMP]
    float* sB = (float*)(dsmem + SA_BYTES);        // [2][KTILE][SMP]
    uint64_t* stash = (uint64_t*)(dsmem + SA_BYTES + SB_BYTES); // [16][512]

    const int tid  = threadIdx.x;
    const int warp = tid >> 5;       // 0..15
    const int lane = tid & 31;
    const int nw0  = warp * 8;       // col block for this warp
    const int lm   = lane * 4;       // row block for this lane
    const int m0   = blockIdx.y * 128;
    const int n0   = blockIdx.x * 128;

    uint64_t acc2[4][4];
#pragma unroll
    for (int i = 0; i < 4; i++)
#pragma unroll
        for (int j = 0; j < 4; j++) acc2[i][j] = 0ull;

    const int nk = NH / KTILE;   // 32

    // staging: each thread 2 float4 of A and 2 of B per k-tile
    float4 ra[2], rb[2];
    auto gload = [&](int kt) {
        const int k0 = kt * KTILE;
#pragma unroll
        for (int j = 0; j < 2; j++) {
            int flat = tid + j * 512;          // 0..1023
            int row  = flat >> 3;              // 0..127
            int kk4  = (flat & 7) * 4;         // 0,4,..,28
            ra[j] = *(const float4*)(Ag + (size_t)(m0 + row) * NH + k0 + kk4);
            rb[j] = *(const float4*)(Bg + (size_t)(n0 + row) * NH + k0 + kk4);
        }
    };
    auto sts = [&](int b) {
#pragma unroll
        for (int j = 0; j < 2; j++) {
            int flat = tid + j * 512;
            int row  = flat >> 3;
            int kk4  = (flat & 7) * 4;
            float* a0 = sA + (b * KTILE + kk4) * SMP + row;
            a0[0 * SMP] = ra[j].x;
            a0[1 * SMP] = ra[j].y;
            a0[2 * SMP] = ra[j].z;
            a0[3 * SMP] = ra[j].w;
            float* b0 = sB + (b * KTILE + kk4) * SMP + row;
            b0[0 * SMP] = rb[j].x;
            b0[1 * SMP] = rb[j].y;
            b0[2 * SMP] = rb[j].z;
            b0[3 * SMP] = rb[j].w;
        }
    };

    gload(0);
    sts(0);
    __syncthreads();

    for (int kt = 0; kt < nk; kt++) {
        const int b = kt & 1;
        if (kt + 1 < nk) gload(kt + 1);

        const float* sAb = sA + b * KTILE * SMP;
        const float* sBb = sB + b * KTILE * SMP;
#pragma unroll
        for (int kk = 0; kk < KTILE; kk++) {
            // A: 4 m-values (one lane-strided LDS.128), dup'd to both lanes
            float4 av = *(const float4*)(sAb + kk * SMP + lm);
            uint64_t ad0 = dup2(av.x), ad1 = dup2(av.y);
            uint64_t ad2 = dup2(av.z), ad3 = dup2(av.w);
            // B: 8 col-values = 4 packed pairs, 2 broadcast LDS.128
            const uint64_t* brow = (const uint64_t*)(sBb + kk * SMP + nw0);
            ulonglong2 b01 = *(const ulonglong2*)(brow);
            ulonglong2 b23 = *(const ulonglong2*)(brow + 2);
            acc2[0][0] = fma2(ad0, b01.x, acc2[0][0]);
            acc2[1][0] = fma2(ad1, b01.x, acc2[1][0]);
            acc2[2][0] = fma2(ad2, b01.x, acc2[2][0]);
            acc2[3][0] = fma2(ad3, b01.x, acc2[3][0]);
            acc2[0][1] = fma2(ad0, b01.y, acc2[0][1]);
            acc2[1][1] = fma2(ad1, b01.y, acc2[1][1]);
            acc2[2][1] = fma2(ad2, b01.y, acc2[2][1]);
            acc2[3][1] = fma2(ad3, b01.y, acc2[3][1]);
            acc2[0][2] = fma2(ad0, b23.x, acc2[0][2]);
            acc2[1][2] = fma2(ad1, b23.x, acc2[1][2]);
            acc2[2][2] = fma2(ad2, b23.x, acc2[2][2]);
            acc2[3][2] = fma2(ad3, b23.x, acc2[3][2]);
            acc2[0][3] = fma2(ad0, b23.y, acc2[0][3]);
            acc2[1][3] = fma2(ad1, b23.y, acc2[1][3]);
            acc2[2][3] = fma2(ad2, b23.y, acc2[2][3]);
            acc2[3][3] = fma2(ad3, b23.y, acc2[3][3]);
        }

        // panel boundary k=512 (kt 15): stash panel-1 sums, restart acc
        if (kt == 15) {
#pragma unroll
            for (int i = 0; i < 4; i++)
#pragma unroll
                for (int j = 0; j < 4; j++) {
                    stash[(i * 4 + j) * 512 + tid] = acc2[i][j];
                    acc2[i][j] = 0ull;
                }
        }

        if (kt + 1 < nk) sts(b ^ 1);
        __syncthreads();
    }

    // ------------------------------ epilogue -------------------------------
    // tot = panel1 + panel2 (one rounded add per element, as in R9)
#pragma unroll
    for (int i = 0; i < 4; i++) {
        const int row = m0 + lm + i;
#pragma unroll
        for (int j2 = 0; j2 < 4; j2++) {
            uint64_t tot = add2(stash[(i * 4 + j2) * 512 + tid], acc2[i][j2]);
            float2 dv = unpk2(tot);
#pragma unroll
            for (int h = 0; h < 2; h++) {
                const int c = n0 + nw0 + 2 * j2 + h;
                const size_t off = (size_t)row * NH + c;
                float d = (h == 0) ? dv.x : dv.y;
                if (MODE == 0) {
                    outC[off] = __fadd_rn(d, biasA[c]);
                } else {
                    // reference order:
                    //   mem = ((((0.5*mem) + cur) + d) + bias) - reset(prev)
                    float mo = memBuf[off];
                    float reset = (mo > 1.0f) ? 1.0f : 0.0f;
                    float v = __fadd_rn(__fmul_rn(0.5f, mo), curBuf[off]);
                    v = __fadd_rn(v, d);
                    v = __fadd_rn(v, biasA[c]);
                    v = __fsub_rn(v, reset);
                    memBuf[off] = v;
                    float s = (v > 1.0f) ? 1.0f : 0.0f;
                    spkOut[off] = s;
                    if (DOSUM) ssum[off] = __fadd_rn(ssum[off], s);
                }
            }
        }
    }
}

// ------------------------------ output kernel ------------------------------
__global__ void out_kernel(const float* __restrict__ t,
                           const float* __restrict__ W3,
                           const float* __restrict__ b3,
                           float* __restrict__ out) {
    int idx = blockIdx.x * blockDim.x + threadIdx.x;   // 0 .. NB*NO-1
    if (idx >= NB * NO) return;
    int row = idx / NO;
    int o   = idx - row * NO;
    const float* tr = t  + (size_t)row * NH;
    const float* wr = W3 + (size_t)o * NH;
    float acc = 0.f;
#pragma unroll 8
    for (int k = 0; k < NH; k++)
        acc = fmaf(__ldg(&tr[k]), __ldg(&wr[k]), acc);
    out[idx] = __fadd_rn(acc, b3[o]);
}

// ------------------------------- host launch -------------------------------
extern "C" void kernel_launch(void* const* d_in, const int* in_sizes, int n_in,
                              void* d_out, int out_size) {
    const float* x   = (const float*)d_in[0];
    const float* W1  = (const float*)d_in[1];
    const float* b1  = (const float*)d_in[2];
    const float* V1w = (const float*)d_in[3];
    const float* V1b = (const float*)d_in[4];
    const float* W2  = (const float*)d_in[5];
    const float* b2  = (const float*)d_in[6];
    const float* V2w = (const float*)d_in[7];
    const float* V2b = (const float*)d_in[8];
    const float* W3  = (const float*)d_in[9];
    const float* b3  = (const float*)d_in[10];
    float* out = (float*)d_out;

    void* p;
    float *spk1a, *spk1b, *spk2a, *spk2b, *mem1, *mem2, *cur1, *cur2, *ssum;
    cudaGetSymbolAddress(&p, g_spk1a); spk1a = (float*)p;
    cudaGetSymbolAddress(&p, g_spk1b); spk1b = (float*)p;
    cudaGetSymbolAddress(&p, g_spk2a); spk2a = (float*)p;
    cudaGetSymbolAddress(&p, g_spk2b); spk2b = (float*)p;
    cudaGetSymbolAddress(&p, g_mem1);  mem1  = (float*)p;
    cudaGetSymbolAddress(&p, g_mem2);  mem2  = (float*)p;
    cudaGetSymbolAddress(&p, g_cur1);  cur1  = (float*)p;
    cudaGetSymbolAddress(&p, g_cur2);  cur2  = (float*)p;
    cudaGetSymbolAddress(&p, g_ssum);  ssum  = (float*)p;

    cudaFuncSetAttribute(f32gemm_kernel<0, 0>,
                         cudaFuncAttributeMaxDynamicSharedMemorySize, SMEM_TOTAL);
    cudaFuncSetAttribute(f32gemm_kernel<1, 0>,
                         cudaFuncAttributeMaxDynamicSharedMemorySize, SMEM_TOTAL);
    cudaFuncSetAttribute(f32gemm_kernel<1, 1>,
                         cudaFuncAttributeMaxDynamicSharedMemorySize, SMEM_TOTAL);

    const int nElem = NB * NH;
    init_state_kernel<<<nElem / 256, 256>>>();

    dim3 grid(NH / 128, NB / 128);   // (8, 128)
    dim3 block(512);

    // cur1 = x @ W1^T + b1
    f32gemm_kernel<0, 0><<<grid, block, SMEM_TOTAL>>>(
        x, W1, b1, nullptr, nullptr, nullptr, nullptr, cur1);

    for (int st = 0; st < NSTEPS; st++) {
        const float* s1in = (st & 1) ? spk1b : spk1a;
        float*      s1out = (st & 1) ? spk1a : spk1b;
        const float* s2in = (st & 1) ? spk2b : spk2a;
        float*      s2out = (st & 1) ? spk2a : spk2b;

        // layer 1: mem1 = 0.5*mem1 + cur1 + s1in@V1w^T + V1b - reset; spike
        f32gemm_kernel<1, 0><<<grid, block, SMEM_TOTAL>>>(
            s1in, V1w, V1b, mem1, cur1, s1out, nullptr, nullptr);

        // cur2 = s1out @ W2^T + b2  (separately rounded)
        f32gemm_kernel<0, 0><<<grid, block, SMEM_TOTAL>>>(
            s1out, W2, b2, nullptr, nullptr, nullptr, nullptr, cur2);

        // layer 2: mem2 = 0.5*mem2 + cur2 + s2in@V2w^T + V2b - reset;
        //          spike; ssum += spike
        f32gemm_kernel<1, 1><<<grid, block, SMEM_TOTAL>>>(
            s2in, V2w, V2b, mem2, cur2, s2out, ssum, nullptr);
    }

    // t = ssum/25 (rounded first), then out = t@W3^T + b3
    div25_kernel<<<nElem / 256, 256>>>(ssum);
    out_kernel<<<(NB * NO + 255) / 256, 256>>>(ssum, W3, b3, out);
}

// round 13
// speedup vs baseline: 1.7840x; 1.7840x over previous
#include <cuda_runtime.h>
#include <cstdint>
#include <cstddef>

// ---------------------------------------------------------------------------
// SNN, fp32-faithful, PASSING association (round 9): per output, fp32 FMA
// chain ascending k; K panels [0,512),[512,1024); panel sums combined with
// one rounded add. Schedule-only changes this round:
//  * explicit register double-buffering of per-kk fragments (hides LDS lat)
//  * epilogue: fold -> stage tile to smem -> coalesced float4 RMW pass
//    (fixes 8x sector amplification + MODE1/2 register cliff)
//  * KTILE=32, 512 threads, tile 128x128, stash reused as output tile
// ---------------------------------------------------------------------------

#define NB 16384
#define NH 1024
#define NSTEPS 25
#define NO 10

#define KTILE 32
#define SMP 132        // smem row pitch (floats)
#define TP  132        // output tile pitch (floats)
#define SA_BYTES  (2 * KTILE * SMP * 4)
#define SB_BYTES  (2 * KTILE * SMP * 4)
#define STASH_BYTES (128 * TP * 4)     // 67.6KB >= 64KB u64 stash
#define SMEM_TOTAL (SA_BYTES + SB_BYTES + STASH_BYTES)

// ----------------------------- device scratch ------------------------------
__device__ __align__(16) float g_spk1a[NB * NH];
__device__ __align__(16) float g_spk1b[NB * NH];
__device__ __align__(16) float g_spk2a[NB * NH];
__device__ __align__(16) float g_spk2b[NB * NH];
__device__ __align__(16) float g_mem1[NB * NH];
__device__ __align__(16) float g_mem2[NB * NH];
__device__ __align__(16) float g_cur1[NB * NH];
__device__ __align__(16) float g_cur2[NB * NH];
__device__ __align__(16) float g_ssum[NB * NH];

// --------------------------- f32x2 packed helpers ---------------------------
__device__ __forceinline__ uint64_t dup2(float x) {
    uint64_t d;
    asm("mov.b64 %0, {%1, %2};" : "=l"(d) : "f"(x), "f"(x));
    return d;
}
__device__ __forceinline__ uint64_t fma2(uint64_t a, uint64_t b, uint64_t c) {
    uint64_t d;
    asm("fma.rn.f32x2 %0, %1, %2, %3;" : "=l"(d) : "l"(a), "l"(b), "l"(c));
    return d;
}
__device__ __forceinline__ uint64_t add2(uint64_t a, uint64_t b) {
    uint64_t d;
    asm("add.rn.f32x2 %0, %1, %2;" : "=l"(d) : "l"(a), "l"(b));
    return d;
}
__device__ __forceinline__ float2 unpk2(uint64_t v) {
    float lo, hi;
    asm("mov.b64 {%0, %1}, %2;" : "=f"(lo), "=f"(hi) : "l"(v));
    return make_float2(lo, hi);
}

// ------------------------------- prep kernels ------------------------------
__global__ void init_state_kernel() {
    size_t i = (size_t)blockIdx.x * blockDim.x + threadIdx.x;
    g_mem1[i] = 0.f;
    g_mem2[i] = 0.f;
    g_ssum[i] = 0.f;
    g_spk1a[i] = 0.f;
    g_spk2a[i] = 0.f;
}

__global__ void div25_kernel(float* __restrict__ s) {
    size_t i = (size_t)blockIdx.x * blockDim.x + threadIdx.x;
    s[i] = __fdiv_rn(s[i], 25.0f);
}

// ------------------------------- GEMM kernel -------------------------------
// C[m,n] = sum_k A[m,k]*B[n,k]: panels [0,512),[512,1024), serial ascending
// k within panel, one rounded add to combine (EXACTLY as passing R9).
// 512 threads: warp w -> cols [w*8, w*8+8); lane -> rows [lane*4, lane*4+4).
// acc2[i][j2]: row lm+i, cols (nw0+2*j2, nw0+2*j2+1) packed along n.

// MODE 0: outC = tot + biasA[n]
// MODE 1: mem = 0.5*mem + cur + tot + biasA - reset; spike; [DOSUM] ssum += s
template <int MODE, int DOSUM>
__global__ void __launch_bounds__(512, 1)
f32gemm_kernel(const float* __restrict__ Ag, const float* __restrict__ Bg,
               const float* __restrict__ biasA,
               float* __restrict__ memBuf, const float* __restrict__ curBuf,
               float* __restrict__ spkOut,
               float* __restrict__ ssum, float* __restrict__ outC) {
    extern __shared__ __align__(16) char dsmem[];
    float* sA = (float*)dsmem;                     // [2][KTILE][SMP]
    float* sB = (float*)(dsmem + SA_BYTES);        // [2][KTILE][SMP]
    char*  stashc = dsmem + SA_BYTES + SB_BYTES;
    uint64_t* stash = (uint64_t*)stashc;           // [16][512] during mainloop
    float* tile = (float*)stashc;                  // [128][TP] in epilogue

    const int tid  = threadIdx.x;
    const int warp = tid >> 5;       // 0..15
    const int lane = tid & 31;
    const int nw0  = warp * 8;       // col block for this warp
    const int lm   = lane * 4;       // row block for this lane
    const int m0   = blockIdx.y * 128;
    const int n0   = blockIdx.x * 128;

    uint64_t acc2[4][4];
#pragma unroll
    for (int i = 0; i < 4; i++)
#pragma unroll
        for (int j = 0; j < 4; j++) acc2[i][j] = 0ull;

    const int nk = NH / KTILE;   // 32

    // global staging: each thread 2 float4 of A and 2 of B per k-tile
    float4 ra[2], rb[2];
    auto gload = [&](int kt) {
        const int k0 = kt * KTILE;
#pragma unroll
        for (int j = 0; j < 2; j++) {
            int flat = tid + j * 512;          // 0..1023
            int row  = flat >> 3;              // 0..127
            int kk4  = (flat & 7) * 4;         // 0,4,..,28
            ra[j] = *(const float4*)(Ag + (size_t)(m0 + row) * NH + k0 + kk4);
            rb[j] = *(const float4*)(Bg + (size_t)(n0 + row) * NH + k0 + kk4);
        }
    };
    auto sts = [&](int b) {
#pragma unroll
        for (int j = 0; j < 2; j++) {
            int flat = tid + j * 512;
            int row  = flat >> 3;
            int kk4  = (flat & 7) * 4;
            float* a0 = sA + (b * KTILE + kk4) * SMP + row;
            a0[0 * SMP] = ra[j].x;
            a0[1 * SMP] = ra[j].y;
            a0[2 * SMP] = ra[j].z;
            a0[3 * SMP] = ra[j].w;
            float* b0 = sB + (b * KTILE + kk4) * SMP + row;
            b0[0 * SMP] = rb[j].x;
            b0[1 * SMP] = rb[j].y;
            b0[2 * SMP] = rb[j].z;
            b0[3 * SMP] = rb[j].w;
        }
    };

    gload(0);
    sts(0);
    __syncthreads();

    for (int kt = 0; kt < nk; kt++) {
        const int b = kt & 1;
        if (kt + 1 < nk) gload(kt + 1);

        const float* sAb = sA + b * KTILE * SMP;
        const float* sBb = sB + b * KTILE * SMP;

        // register double-buffered fragments: load kk+1 while kk computes
        float4 av[2];
        ulonglong2 b01[2], b23[2];
        av[0]  = *(const float4*)(sAb + lm);
        {
            const uint64_t* br = (const uint64_t*)(sBb + nw0);
            b01[0] = *(const ulonglong2*)(br);
            b23[0] = *(const ulonglong2*)(br + 2);
        }
#pragma unroll
        for (int kk = 0; kk < KTILE; kk++) {
            const int cur = kk & 1, nxt = cur ^ 1;
            if (kk + 1 < KTILE) {
                av[nxt] = *(const float4*)(sAb + (kk + 1) * SMP + lm);
                const uint64_t* br =
                    (const uint64_t*)(sBb + (kk + 1) * SMP + nw0);
                b01[nxt] = *(const ulonglong2*)(br);
                b23[nxt] = *(const ulonglong2*)(br + 2);
            }
            uint64_t ad0 = dup2(av[cur].x), ad1 = dup2(av[cur].y);
            uint64_t ad2 = dup2(av[cur].z), ad3 = dup2(av[cur].w);
            acc2[0][0] = fma2(ad0, b01[cur].x, acc2[0][0]);
            acc2[1][0] = fma2(ad1, b01[cur].x, acc2[1][0]);
            acc2[2][0] = fma2(ad2, b01[cur].x, acc2[2][0]);
            acc2[3][0] = fma2(ad3, b01[cur].x, acc2[3][0]);
            acc2[0][1] = fma2(ad0, b01[cur].y, acc2[0][1]);
            acc2[1][1] = fma2(ad1, b01[cur].y, acc2[1][1]);
            acc2[2][1] = fma2(ad2, b01[cur].y, acc2[2][1]);
            acc2[3][1] = fma2(ad3, b01[cur].y, acc2[3][1]);
            acc2[0][2] = fma2(ad0, b23[cur].x, acc2[0][2]);
            acc2[1][2] = fma2(ad1, b23[cur].x, acc2[1][2]);
            acc2[2][2] = fma2(ad2, b23[cur].x, acc2[2][2]);
            acc2[3][2] = fma2(ad3, b23[cur].x, acc2[3][2]);
            acc2[0][3] = fma2(ad0, b23[cur].y, acc2[0][3]);
            acc2[1][3] = fma2(ad1, b23[cur].y, acc2[1][3]);
            acc2[2][3] = fma2(ad2, b23[cur].y, acc2[2][3]);
            acc2[3][3] = fma2(ad3, b23[cur].y, acc2[3][3]);
        }

        // panel boundary k=512 (kt 15): stash panel-1 sums, restart acc
        if (kt == 15) {
#pragma unroll
            for (int i = 0; i < 4; i++)
#pragma unroll
                for (int j = 0; j < 4; j++) {
                    stash[(i * 4 + j) * 512 + tid] = acc2[i][j];
                    acc2[i][j] = 0ull;
                }
        }

        if (kt + 1 < nk) sts(b ^ 1);
        __syncthreads();
    }

    // ------------------------------ epilogue -------------------------------
    // 1) fold: tot = panel1 + panel2 (one rounded add, as in R9)
    uint64_t tot2[4][4];
#pragma unroll
    for (int i = 0; i < 4; i++)
#pragma unroll
        for (int j = 0; j < 4; j++)
            tot2[i][j] = add2(stash[(i * 4 + j) * 512 + tid], acc2[i][j]);
    __syncthreads();   // all folds done before stash is overwritten as tile

    // 2) stage tile to smem in (row, col) layout
#pragma unroll
    for (int i = 0; i < 4; i++) {
        const int row = lm + i;
#pragma unroll
        for (int j = 0; j < 4; j++) {
            float2 dv = unpk2(tot2[i][j]);
            *(float2*)&tile[row * TP + nw0 + 2 * j] = dv;
        }
    }
    __syncthreads();

    // 3) coalesced float4 pass: warp -> row, lane -> 4 consecutive cols
#pragma unroll
    for (int it = 0; it < 8; it++) {
        const int row = it * 16 + warp;
        const int col = lane * 4;
        float4 dv = *(const float4*)&tile[row * TP + col];
        const int c = n0 + col;
        const size_t off = (size_t)(m0 + row) * NH + c;
        float4 bias = *(const float4*)&biasA[c];
        if (MODE == 0) {
            float4 o;
            o.x = __fadd_rn(dv.x, bias.x);
            o.y = __fadd_rn(dv.y, bias.y);
            o.z = __fadd_rn(dv.z, bias.z);
            o.w = __fadd_rn(dv.w, bias.w);
            *(float4*)&outC[off] = o;
        } else {
            float4 mo = *(const float4*)&memBuf[off];
            float4 cu = *(const float4*)&curBuf[off];
            float4 nm, sp;
            {
                // reference order per element:
                //   mem = ((((0.5*mem) + cur) + d) + bias) - reset(prev)
                float v;
                v = __fadd_rn(__fmul_rn(0.5f, mo.x), cu.x);
                v = __fadd_rn(v, dv.x); v = __fadd_rn(v, bias.x);
                nm.x = __fsub_rn(v, (mo.x > 1.0f) ? 1.0f : 0.0f);
                v = __fadd_rn(__fmul_rn(0.5f, mo.y), cu.y);
                v = __fadd_rn(v, dv.y); v = __fadd_rn(v, bias.y);
                nm.y = __fsub_rn(v, (mo.y > 1.0f) ? 1.0f : 0.0f);
                v = __fadd_rn(__fmul_rn(0.5f, mo.z), cu.z);
                v = __fadd_rn(v, dv.z); v = __fadd_rn(v, bias.z);
                nm.z = __fsub_rn(v, (mo.z > 1.0f) ? 1.0f : 0.0f);
                v = __fadd_rn(__fmul_rn(0.5f, mo.w), cu.w);
                v = __fadd_rn(v, dv.w); v = __fadd_rn(v, bias.w);
                nm.w = __fsub_rn(v, (mo.w > 1.0f) ? 1.0f : 0.0f);
            }
            *(float4*)&memBuf[off] = nm;
            sp.x = (nm.x > 1.0f) ? 1.0f : 0.0f;
            sp.y = (nm.y > 1.0f) ? 1.0f : 0.0f;
            sp.z = (nm.z > 1.0f) ? 1.0f : 0.0f;
            sp.w = (nm.w > 1.0f) ? 1.0f : 0.0f;
            *(float4*)&spkOut[off] = sp;
            if (DOSUM) {
                float4 ss = *(const float4*)&ssum[off];
                ss.x = __fadd_rn(ss.x, sp.x);
                ss.y = __fadd_rn(ss.y, sp.y);
                ss.z = __fadd_rn(ss.z, sp.z);
                ss.w = __fadd_rn(ss.w, sp.w);
                *(float4*)&ssum[off] = ss;
            }
        }
    }
}

// ------------------------------ output kernel ------------------------------
__global__ void out_kernel(const float* __restrict__ t,
                           const float* __restrict__ W3,
                           const float* __restrict__ b3,
                           float* __restrict__ out) {
    int idx = blockIdx.x * blockDim.x + threadIdx.x;   // 0 .. NB*NO-1
    if (idx >= NB * NO) return;
    int row = idx / NO;
    int o   = idx - row * NO;
    const float* tr = t  + (size_t)row * NH;
    const float* wr = W3 + (size_t)o * NH;
    float acc = 0.f;
#pragma unroll 8
    for (int k = 0; k < NH; k++)
        acc = fmaf(__ldg(&tr[k]), __ldg(&wr[k]), acc);
    out[idx] = __fadd_rn(acc, b3[o]);
}

// ------------------------------- host launch -------------------------------
extern "C" void kernel_launch(void* const* d_in, const int* in_sizes, int n_in,
                              void* d_out, int out_size) {
    const float* x   = (const float*)d_in[0];
    const float* W1  = (const float*)d_in[1];
    const float* b1  = (const float*)d_in[2];
    const float* V1w = (const float*)d_in[3];
    const float* V1b = (const float*)d_in[4];
    const float* W2  = (const float*)d_in[5];
    const float* b2  = (const float*)d_in[6];
    const float* V2w = (const float*)d_in[7];
    const float* V2b = (const float*)d_in[8];
    const float* W3  = (const float*)d_in[9];
    const float* b3  = (const float*)d_in[10];
    float* out = (float*)d_out;

    void* p;
    float *spk1a, *spk1b, *spk2a, *spk2b, *mem1, *mem2, *cur1, *cur2, *ssum;
    cudaGetSymbolAddress(&p, g_spk1a); spk1a = (float*)p;
    cudaGetSymbolAddress(&p, g_spk1b); spk1b = (float*)p;
    cudaGetSymbolAddress(&p, g_spk2a); spk2a = (float*)p;
    cudaGetSymbolAddress(&p, g_spk2b); spk2b = (float*)p;
    cudaGetSymbolAddress(&p, g_mem1);  mem1  = (float*)p;
    cudaGetSymbolAddress(&p, g_mem2);  mem2  = (float*)p;
    cudaGetSymbolAddress(&p, g_cur1);  cur1  = (float*)p;
    cudaGetSymbolAddress(&p, g_cur2);  cur2  = (float*)p;
    cudaGetSymbolAddress(&p, g_ssum);  ssum  = (float*)p;

    cudaFuncSetAttribute(f32gemm_kernel<0, 0>,
                         cudaFuncAttributeMaxDynamicSharedMemorySize, SMEM_TOTAL);
    cudaFuncSetAttribute(f32gemm_kernel<1, 0>,
                         cudaFuncAttributeMaxDynamicSharedMemorySize, SMEM_TOTAL);
    cudaFuncSetAttribute(f32gemm_kernel<1, 1>,
                         cudaFuncAttributeMaxDynamicSharedMemorySize, SMEM_TOTAL);

    const int nElem = NB * NH;
    init_state_kernel<<<nElem / 256, 256>>>();

    dim3 grid(NH / 128, NB / 128);   // (8, 128)
    dim3 block(512);

    // cur1 = x @ W1^T + b1
    f32gemm_kernel<0, 0><<<grid, block, SMEM_TOTAL>>>(
        x, W1, b1, nullptr, nullptr, nullptr, nullptr, cur1);

    for (int st = 0; st < NSTEPS; st++) {
        const float* s1in = (st & 1) ? spk1b : spk1a;
        float*      s1out = (st & 1) ? spk1a : spk1b;
        const float* s2in = (st & 1) ? spk2b : spk2a;
        float*      s2out = (st & 1) ? spk2a : spk2b;

        // layer 1: mem1 = 0.5*mem1 + cur1 + s1in@V1w^T + V1b - reset; spike
        f32gemm_kernel<1, 0><<<grid, block, SMEM_TOTAL>>>(
            s1in, V1w, V1b, mem1, cur1, s1out, nullptr, nullptr);

        // cur2 = s1out @ W2^T + b2  (separately rounded)
        f32gemm_kernel<0, 0><<<grid, block, SMEM_TOTAL>>>(
            s1out, W2, b2, nullptr, nullptr, nullptr, nullptr, cur2);

        // layer 2: mem2 = 0.5*mem2 + cur2 + s2in@V2w^T + V2b - reset;
        //          spike; ssum += spike
        f32gemm_kernel<1, 1><<<grid, block, SMEM_TOTAL>>>(
            s2in, V2w, V2b, mem2, cur2, s2out, ssum, nullptr);
    }

    // t = ssum/25 (rounded first), then out = t@W3^T + b3
    div25_kernel<<<nElem / 256, 256>>>(ssum);
    out_kernel<<<(NB * NO + 255) / 256, 256>>>(ssum, W3, b3, out);
}

// round 14
// speedup vs baseline: 2.1247x; 1.1910x over previous
#include <cuda_runtime.h>
#include <cstdint>
#include <cstddef>

// ---------------------------------------------------------------------------
// SNN, fp32-faithful, PASSING association (round 9): per output, fp32 FMA
// chain ascending k; K panels [0,512),[512,1024); panel sums combined with
// one rounded add. Schedule-only changes this round:
//  * 256 threads/CTA, 2 CTAs/SM (cross-CTA barrier/latency overlap at the
//    same 16 warps/SM) -- attacks the 40% issue / 59% fma bubble of R13
//  * per-thread 4m x 16n packed-n accumulators (64 regs), lean fragments
//  * KTILE=16; stash + coalesced smem-tile epilogue kept from R13
// ---------------------------------------------------------------------------

#define NB 16384
#define NH 1024
#define NSTEPS 25
#define NO 10

#define KTILE 16
#define SMP 132        // smem row pitch (floats)
#define TP  132        // output tile pitch (floats)
#define SA_BYTES  (2 * KTILE * SMP * 4)
#define SB_BYTES  (2 * KTILE * SMP * 4)
#define STASH_BYTES (128 * TP * 4)     // 67.6KB; >= 64KB u64 stash
#define SMEM_TOTAL (SA_BYTES + SB_BYTES + STASH_BYTES)   // ~101.4KB

// ----------------------------- device scratch ------------------------------
__device__ __align__(16) float g_spk1a[NB * NH];
__device__ __align__(16) float g_spk1b[NB * NH];
__device__ __align__(16) float g_spk2a[NB * NH];
__device__ __align__(16) float g_spk2b[NB * NH];
__device__ __align__(16) float g_mem1[NB * NH];
__device__ __align__(16) float g_mem2[NB * NH];
__device__ __align__(16) float g_cur1[NB * NH];
__device__ __align__(16) float g_cur2[NB * NH];
__device__ __align__(16) float g_ssum[NB * NH];

// --------------------------- f32x2 packed helpers ---------------------------
__device__ __forceinline__ uint64_t dup2(float x) {
    uint64_t d;
    asm("mov.b64 %0, {%1, %2};" : "=l"(d) : "f"(x), "f"(x));
    return d;
}
__device__ __forceinline__ uint64_t fma2(uint64_t a, uint64_t b, uint64_t c) {
    uint64_t d;
    asm("fma.rn.f32x2 %0, %1, %2, %3;" : "=l"(d) : "l"(a), "l"(b), "l"(c));
    return d;
}
__device__ __forceinline__ uint64_t add2(uint64_t a, uint64_t b) {
    uint64_t d;
    asm("add.rn.f32x2 %0, %1, %2;" : "=l"(d) : "l"(a), "l"(b));
    return d;
}
__device__ __forceinline__ float2 unpk2(uint64_t v) {
    float lo, hi;
    asm("mov.b64 {%0, %1}, %2;" : "=f"(lo), "=f"(hi) : "l"(v));
    return make_float2(lo, hi);
}

// ------------------------------- prep kernels ------------------------------
__global__ void init_state_kernel() {
    size_t i = (size_t)blockIdx.x * blockDim.x + threadIdx.x;
    g_mem1[i] = 0.f;
    g_mem2[i] = 0.f;
    g_ssum[i] = 0.f;
    g_spk1a[i] = 0.f;
    g_spk2a[i] = 0.f;
}

__global__ void div25_kernel(float* __restrict__ s) {
    size_t i = (size_t)blockIdx.x * blockDim.x + threadIdx.x;
    s[i] = __fdiv_rn(s[i], 25.0f);
}

// ------------------------------- GEMM kernel -------------------------------
// C[m,n] = sum_k A[m,k]*B[n,k]: panels [0,512),[512,1024), serial ascending
// k within panel, one rounded add to combine (EXACTLY as passing R9).
// 256 threads, tile 128x128: warp w -> cols [w*16, w*16+16);
// lane -> rows [lane*4, lane*4+4). acc2[i][j]: row lm+i, cols nw0+2j,+1.

// MODE 0: outC = tot + biasA[n]
// MODE 1: mem = 0.5*mem + cur + tot + biasA - reset; spike; [DOSUM] ssum += s
template <int MODE, int DOSUM>
__global__ void __launch_bounds__(256, 2)
f32gemm_kernel(const float* __restrict__ Ag, const float* __restrict__ Bg,
               const float* __restrict__ biasA,
               float* __restrict__ memBuf, const float* __restrict__ curBuf,
               float* __restrict__ spkOut,
               float* __restrict__ ssum, float* __restrict__ outC) {
    extern __shared__ __align__(16) char dsmem[];
    float* sA = (float*)dsmem;                     // [2][KTILE][SMP]
    float* sB = (float*)(dsmem + SA_BYTES);        // [2][KTILE][SMP]
    char*  stashc = dsmem + SA_BYTES + SB_BYTES;
    uint64_t* stash = (uint64_t*)stashc;           // [32][256] during mainloop
    float* tile = (float*)stashc;                  // [128][TP] in epilogue

    const int tid  = threadIdx.x;
    const int warp = tid >> 5;       // 0..7
    const int lane = tid & 31;
    const int nw0  = warp * 16;      // col block for this warp
    const int lm   = lane * 4;       // row block for this lane
    const int m0   = blockIdx.y * 128;
    const int n0   = blockIdx.x * 128;

    uint64_t acc2[4][8];
#pragma unroll
    for (int i = 0; i < 4; i++)
#pragma unroll
        for (int j = 0; j < 8; j++) acc2[i][j] = 0ull;

    const int nk = NH / KTILE;   // 64

    // global staging: each thread 2 float4 of A and 2 of B per k-tile
    float4 ra[2], rb[2];
    auto gload = [&](int kt) {
        const int k0 = kt * KTILE;
#pragma unroll
        for (int j = 0; j < 2; j++) {
            int flat = tid + j * 256;          // 0..511
            int row  = flat >> 2;              // 0..127
            int kk4  = (flat & 3) * 4;         // 0,4,8,12
            ra[j] = *(const float4*)(Ag + (size_t)(m0 + row) * NH + k0 + kk4);
            rb[j] = *(const float4*)(Bg + (size_t)(n0 + row) * NH + k0 + kk4);
        }
    };
    auto sts = [&](int b) {
#pragma unroll
        for (int j = 0; j < 2; j++) {
            int flat = tid + j * 256;
            int row  = flat >> 2;
            int kk4  = (flat & 3) * 4;
            float* a0 = sA + (b * KTILE + kk4) * SMP + row;
            a0[0 * SMP] = ra[j].x;
            a0[1 * SMP] = ra[j].y;
            a0[2 * SMP] = ra[j].z;
            a0[3 * SMP] = ra[j].w;
            float* b0 = sB + (b * KTILE + kk4) * SMP + row;
            b0[0 * SMP] = rb[j].x;
            b0[1 * SMP] = rb[j].y;
            b0[2 * SMP] = rb[j].z;
            b0[3 * SMP] = rb[j].w;
        }
    };

    gload(0);
    sts(0);
    __syncthreads();

    for (int kt = 0; kt < nk; kt++) {
        const int b = kt & 1;
        if (kt + 1 < nk) gload(kt + 1);

        const float* sAb = sA + b * KTILE * SMP;
        const float* sBb = sB + b * KTILE * SMP;
#pragma unroll
        for (int kk = 0; kk < KTILE; kk++) {
            // A: 4 m-values (one lane-strided LDS.128), dup'd to both lanes
            float4 av = *(const float4*)(sAb + kk * SMP + lm);
            uint64_t ad0 = dup2(av.x), ad1 = dup2(av.y);
            uint64_t ad2 = dup2(av.z), ad3 = dup2(av.w);
            // B: 16 col-values = 8 packed pairs, 4 broadcast LDS.128
            const uint64_t* brow = (const uint64_t*)(sBb + kk * SMP + nw0);
#pragma unroll
            for (int q = 0; q < 4; q++) {
                ulonglong2 bp = *(const ulonglong2*)(brow + 2 * q);
                const int j0 = 2 * q;
                acc2[0][j0]     = fma2(ad0, bp.x, acc2[0][j0]);
                acc2[1][j0]     = fma2(ad1, bp.x, acc2[1][j0]);
                acc2[2][j0]     = fma2(ad2, bp.x, acc2[2][j0]);
                acc2[3][j0]     = fma2(ad3, bp.x, acc2[3][j0]);
                acc2[0][j0 + 1] = fma2(ad0, bp.y, acc2[0][j0 + 1]);
                acc2[1][j0 + 1] = fma2(ad1, bp.y, acc2[1][j0 + 1]);
                acc2[2][j0 + 1] = fma2(ad2, bp.y, acc2[2][j0 + 1]);
                acc2[3][j0 + 1] = fma2(ad3, bp.y, acc2[3][j0 + 1]);
            }
        }

        // panel boundary k=512 (kt 31): stash panel-1 sums, restart acc
        if (kt == 31) {
#pragma unroll
            for (int i = 0; i < 4; i++)
#pragma unroll
                for (int j = 0; j < 8; j++) {
                    stash[(i * 8 + j) * 256 + tid] = acc2[i][j];
                    acc2[i][j] = 0ull;
                }
        }

        if (kt + 1 < nk) sts(b ^ 1);
        __syncthreads();
    }

    // ------------------------------ epilogue -------------------------------
    // 1) fold: tot = panel1 + panel2 (one rounded add, as in R9)
    uint64_t tot2[4][8];
#pragma unroll
    for (int i = 0; i < 4; i++)
#pragma unroll
        for (int j = 0; j < 8; j++)
            tot2[i][j] = add2(stash[(i * 8 + j) * 256 + tid], acc2[i][j]);
    __syncthreads();   // all folds done before stash is overwritten as tile

    // 2) stage tile to smem in (row, col) layout
#pragma unroll
    for (int i = 0; i < 4; i++) {
        const int row = lm + i;
#pragma unroll
        for (int j = 0; j < 8; j++) {
            float2 dv = unpk2(tot2[i][j]);
            *(float2*)&tile[row * TP + nw0 + 2 * j] = dv;
        }
    }
    __syncthreads();

    // 3) coalesced float4 pass: warp -> row, lane -> 4 consecutive cols
#pragma unroll
    for (int it = 0; it < 16; it++) {
        const int row = it * 8 + warp;
        const int col = lane * 4;
        float4 dv = *(const float4*)&tile[row * TP + col];
        const int c = n0 + col;
        const size_t off = (size_t)(m0 + row) * NH + c;
        float4 bias = *(const float4*)&biasA[c];
        if (MODE == 0) {
            float4 o;
            o.x = __fadd_rn(dv.x, bias.x);
            o.y = __fadd_rn(dv.y, bias.y);
            o.z = __fadd_rn(dv.z, bias.z);
            o.w = __fadd_rn(dv.w, bias.w);
            *(float4*)&outC[off] = o;
        } else {
            float4 mo = *(const float4*)&memBuf[off];
            float4 cu = *(const float4*)&curBuf[off];
            float4 nm, sp;
            {
                // reference order per element:
                //   mem = ((((0.5*mem) + cur) + d) + bias) - reset(prev)
                float v;
                v = __fadd_rn(__fmul_rn(0.5f, mo.x), cu.x);
                v = __fadd_rn(v, dv.x); v = __fadd_rn(v, bias.x);
                nm.x = __fsub_rn(v, (mo.x > 1.0f) ? 1.0f : 0.0f);
                v = __fadd_rn(__fmul_rn(0.5f, mo.y), cu.y);
                v = __fadd_rn(v, dv.y); v = __fadd_rn(v, bias.y);
                nm.y = __fsub_rn(v, (mo.y > 1.0f) ? 1.0f : 0.0f);
                v = __fadd_rn(__fmul_rn(0.5f, mo.z), cu.z);
                v = __fadd_rn(v, dv.z); v = __fadd_rn(v, bias.z);
                nm.z = __fsub_rn(v, (mo.z > 1.0f) ? 1.0f : 0.0f);
                v = __fadd_rn(__fmul_rn(0.5f, mo.w), cu.w);
                v = __fadd_rn(v, dv.w); v = __fadd_rn(v, bias.w);
                nm.w = __fsub_rn(v, (mo.w > 1.0f) ? 1.0f : 0.0f);
            }
            *(float4*)&memBuf[off] = nm;
            sp.x = (nm.x > 1.0f) ? 1.0f : 0.0f;
            sp.y = (nm.y > 1.0f) ? 1.0f : 0.0f;
            sp.z = (nm.z > 1.0f) ? 1.0f : 0.0f;
            sp.w = (nm.w > 1.0f) ? 1.0f : 0.0f;
            *(float4*)&spkOut[off] = sp;
            if (DOSUM) {
                float4 ss = *(const float4*)&ssum[off];
                ss.x = __fadd_rn(ss.x, sp.x);
                ss.y = __fadd_rn(ss.y, sp.y);
                ss.z = __fadd_rn(ss.z, sp.z);
                ss.w = __fadd_rn(ss.w, sp.w);
                *(float4*)&ssum[off] = ss;
            }
        }
    }
}

// ------------------------------ output kernel ------------------------------
__global__ void out_kernel(const float* __restrict__ t,
                           const float* __restrict__ W3,
                           const float* __restrict__ b3,
                           float* __restrict__ out) {
    int idx = blockIdx.x * blockDim.x + threadIdx.x;   // 0 .. NB*NO-1
    if (idx >= NB * NO) return;
    int row = idx / NO;
    int o   = idx - row * NO;
    const float* tr = t  + (size_t)row * NH;
    const float* wr = W3 + (size_t)o * NH;
    float acc = 0.f;
#pragma unroll 8
    for (int k = 0; k < NH; k++)
        acc = fmaf(__ldg(&tr[k]), __ldg(&wr[k]), acc);
    out[idx] = __fadd_rn(acc, b3[o]);
}

// ------------------------------- host launch -------------------------------
extern "C" void kernel_launch(void* const* d_in, const int* in_sizes, int n_in,
                              void* d_out, int out_size) {
    const float* x   = (const float*)d_in[0];
    const float* W1  = (const float*)d_in[1];
    const float* b1  = (const float*)d_in[2];
    const float* V1w = (const float*)d_in[3];
    const float* V1b = (const float*)d_in[4];
    const float* W2  = (const float*)d_in[5];
    const float* b2  = (const float*)d_in[6];
    const float* V2w = (const float*)d_in[7];
    const float* V2b = (const float*)d_in[8];
    const float* W3  = (const float*)d_in[9];
    const float* b3  = (const float*)d_in[10];
    float* out = (float*)d_out;

    void* p;
    float *spk1a, *spk1b, *spk2a, *spk2b, *mem1, *mem2, *cur1, *cur2, *ssum;
    cudaGetSymbolAddress(&p, g_spk1a); spk1a = (float*)p;
    cudaGetSymbolAddress(&p, g_spk1b); spk1b = (float*)p;
    cudaGetSymbolAddress(&p, g_spk2a); spk2a = (float*)p;
    cudaGetSymbolAddress(&p, g_spk2b); spk2b = (float*)p;
    cudaGetSymbolAddress(&p, g_mem1);  mem1  = (float*)p;
    cudaGetSymbolAddress(&p, g_mem2);  mem2  = (float*)p;
    cudaGetSymbolAddress(&p, g_cur1);  cur1  = (float*)p;
    cudaGetSymbolAddress(&p, g_cur2);  cur2  = (float*)p;
    cudaGetSymbolAddress(&p, g_ssum);  ssum  = (float*)p;

    cudaFuncSetAttribute(f32gemm_kernel<0, 0>,
                         cudaFuncAttributeMaxDynamicSharedMemorySize, SMEM_TOTAL);
    cudaFuncSetAttribute(f32gemm_kernel<1, 0>,
                         cudaFuncAttributeMaxDynamicSharedMemorySize, SMEM_TOTAL);
    cudaFuncSetAttribute(f32gemm_kernel<1, 1>,
                         cudaFuncAttributeMaxDynamicSharedMemorySize, SMEM_TOTAL);

    const int nElem = NB * NH;
    init_state_kernel<<<nElem / 256, 256>>>();

    dim3 grid(NH / 128, NB / 128);   // (8, 128)
    dim3 block(256);

    // cur1 = x @ W1^T + b1
    f32gemm_kernel<0, 0><<<grid, block, SMEM_TOTAL>>>(
        x, W1, b1, nullptr, nullptr, nullptr, nullptr, cur1);

    for (int st = 0; st < NSTEPS; st++) {
        const float* s1in = (st & 1) ? spk1b : spk1a;
        float*      s1out = (st & 1) ? spk1a : spk1b;
        const float* s2in = (st & 1) ? spk2b : spk2a;
        float*      s2out = (st & 1) ? spk2a : spk2b;

        // layer 1: mem1 = 0.5*mem1 + cur1 + s1in@V1w^T + V1b - reset; spike
        f32gemm_kernel<1, 0><<<grid, block, SMEM_TOTAL>>>(
            s1in, V1w, V1b, mem1, cur1, s1out, nullptr, nullptr);

        // cur2 = s1out @ W2^T + b2  (separately rounded)
        f32gemm_kernel<0, 0><<<grid, block, SMEM_TOTAL>>>(
            s1out, W2, b2, nullptr, nullptr, nullptr, nullptr, cur2);

        // layer 2: mem2 = 0.5*mem2 + cur2 + s2in@V2w^T + V2b - reset;
        //          spike; ssum += spike
        f32gemm_kernel<1, 1><<<grid, block, SMEM_TOTAL>>>(
            s2in, V2w, V2b, mem2, cur2, s2out, ssum, nullptr);
    }

    // t = ssum/25 (rounded first), then out = t@W3^T + b3
    div25_kernel<<<nElem / 256, 256>>>(ssum);
    out_kernel<<<(NB * NO + 255) / 256, 256>>>(ssum, W3, b3, out);
}

// round 15
// speedup vs baseline: 2.1390x; 1.0067x over previous
#include <cuda_runtime.h>
#include <cstdint>
#include <cstddef>

// ---------------------------------------------------------------------------
// SNN, fp32-faithful, PASSING association (round 9): per output, fp32 FMA
// chain ascending k; K panels [0,512),[512,1024); panel sums combined with
// one rounded add. Schedule-only changes this round:
//  * A operands pre-transposed ONCE (x, weights) / spikes written transposed
//    by the epilogue -> both GEMM tiles load via cp.async straight into the
//    k-major smem layout (no LDG staging registers, no manual transpose)
//  * frees ~20 regs (R14 was pinned at the 128-reg 2-CTA cap) so ptxas can
//    pipeline smem fragments
//  * 256 thr/CTA, 2 CTAs/SM, KTILE=16, stash + coalesced epilogue from R14
// ---------------------------------------------------------------------------

#define NB 16384
#define NH 1024
#define NSTEPS 25
#define NO 10

#define KTILE 16
#define SMP 132        // smem row pitch (floats)
#define TP  132        // output tile pitch (floats)
#define SA_BYTES  (2 * KTILE * SMP * 4)
#define SB_BYTES  (2 * KTILE * SMP * 4)
#define STASH_BYTES (128 * TP * 4)     // 67.6KB; >= 64KB u64 stash
#define SMEM_TOTAL (SA_BYTES + SB_BYTES + STASH_BYTES)   // ~101.4KB

// ----------------------------- device scratch ------------------------------
// transposed spike buffers: [feature][batch]
__device__ __align__(16) float g_spk1aT[NH * NB];
__device__ __align__(16) float g_spk1bT[NH * NB];
__device__ __align__(16) float g_spk2aT[NH * NB];
__device__ __align__(16) float g_spk2bT[NH * NB];
__device__ __align__(16) float g_mem1[NB * NH];
__device__ __align__(16) float g_mem2[NB * NH];
__device__ __align__(16) float g_cur1[NB * NH];
__device__ __align__(16) float g_cur2[NB * NH];
__device__ __align__(16) float g_ssum[NB * NH];
__device__ __align__(16) float g_xT [NH * NB];    // x transposed
__device__ __align__(16) float g_W1T[NH * NH];    // weights [k][n]
__device__ __align__(16) float g_V1T[NH * NH];
__device__ __align__(16) float g_W2T[NH * NH];
__device__ __align__(16) float g_V2T[NH * NH];

// --------------------------- f32x2 packed helpers ---------------------------
__device__ __forceinline__ uint64_t dup2(float x) {
    uint64_t d;
    asm("mov.b64 %0, {%1, %2};" : "=l"(d) : "f"(x), "f"(x));
    return d;
}
__device__ __forceinline__ uint64_t fma2(uint64_t a, uint64_t b, uint64_t c) {
    uint64_t d;
    asm("fma.rn.f32x2 %0, %1, %2, %3;" : "=l"(d) : "l"(a), "l"(b), "l"(c));
    return d;
}
__device__ __forceinline__ uint64_t add2(uint64_t a, uint64_t b) {
    uint64_t d;
    asm("add.rn.f32x2 %0, %1, %2;" : "=l"(d) : "l"(a), "l"(b));
    return d;
}
__device__ __forceinline__ float2 unpk2(uint64_t v) {
    float lo, hi;
    asm("mov.b64 {%0, %1}, %2;" : "=f"(lo), "=f"(hi) : "l"(v));
    return make_float2(lo, hi);
}
__device__ __forceinline__ uint32_t smem_u32(const void* p) {
    return (uint32_t)__cvta_generic_to_shared(p);
}
__device__ __forceinline__ void cpasync16(uint32_t dst, const void* src) {
    asm volatile("cp.async.cg.shared.global [%0], [%1], 16;\n"
                 :: "r"(dst), "l"(src));
}

// ------------------------------- prep kernels ------------------------------
__global__ void init_state_kernel() {
    size_t i = (size_t)blockIdx.x * blockDim.x + threadIdx.x;
    g_mem1[i] = 0.f;
    g_mem2[i] = 0.f;
    g_ssum[i] = 0.f;
    g_spk1aT[i] = 0.f;
    g_spk2aT[i] = 0.f;
}

__global__ void div25_kernel(float* __restrict__ s) {
    size_t i = (size_t)blockIdx.x * blockDim.x + threadIdx.x;
    s[i] = __fdiv_rn(s[i], 25.0f);
}

// tiled transpose: in [R][C] -> out [C][R]; R, C multiples of 32
__global__ void transpose_kernel(const float* __restrict__ in,
                                 float* __restrict__ out, int R, int C) {
    __shared__ float t[32][33];
    const int c0 = blockIdx.x * 32;
    const int r0 = blockIdx.y * 32;
    const int tx = threadIdx.x;      // 0..31
    const int ty = threadIdx.y;      // 0..7
#pragma unroll
    for (int i = 0; i < 4; i++)
        t[ty + 8 * i][tx] = in[(size_t)(r0 + ty + 8 * i) * C + c0 + tx];
    __syncthreads();
#pragma unroll
    for (int i = 0; i < 4; i++)
        out[(size_t)(c0 + ty + 8 * i) * R + r0 + tx] = t[tx][ty + 8 * i];
}

// ------------------------------- GEMM kernel -------------------------------
// C[m,n] = sum_k AT[k,m]*BT[k,n]: panels [0,512),[512,1024), serial ascending
// k within panel, one rounded add to combine (EXACTLY as passing R9).
// 256 threads, tile 128x128: warp w -> cols [w*16, w*16+16);
// lane -> rows [lane*4, lane*4+4). Both operands cp.async'd (already k-major).
// AM = row count of AT's second dim (NB for data, used for addressing).

// MODE 0: outC = tot + biasA[n]
// MODE 1: mem = 0.5*mem + cur + tot + biasA - reset; spike -> spkT; [DOSUM]
template <int MODE, int DOSUM>
__global__ void __launch_bounds__(256, 2)
f32gemm_kernel(const float* __restrict__ AT, const float* __restrict__ BT,
               const float* __restrict__ biasA,
               float* __restrict__ memBuf, const float* __restrict__ curBuf,
               float* __restrict__ spkT,
               float* __restrict__ ssum, float* __restrict__ outC) {
    extern __shared__ __align__(16) char dsmem[];
    float* sA = (float*)dsmem;                     // [2][KTILE][SMP]
    float* sB = (float*)(dsmem + SA_BYTES);        // [2][KTILE][SMP]
    char*  stashc = dsmem + SA_BYTES + SB_BYTES;
    uint64_t* stash = (uint64_t*)stashc;           // [32][256] during mainloop
    float* tile = (float*)stashc;                  // [128][TP] in epilogue

    const uint32_t sAu = smem_u32(sA);
    const uint32_t sBu = smem_u32(sB);

    const int tid  = threadIdx.x;
    const int warp = tid >> 5;       // 0..7
    const int lane = tid & 31;
    const int nw0  = warp * 16;      // col block for this warp
    const int lm   = lane * 4;       // row block for this lane
    const int m0   = blockIdx.y * 128;
    const int n0   = blockIdx.x * 128;

    uint64_t acc2[4][8];
#pragma unroll
    for (int i = 0; i < 4; i++)
#pragma unroll
        for (int j = 0; j < 8; j++) acc2[i][j] = 0ull;

    const int nk = NH / KTILE;   // 64

    // cp.async staging: 2 A chunks + 2 B chunks (16B each) per thread/ktile
    auto stage = [&](int kt, int b) {
        const int k0 = kt * KTILE;
#pragma unroll
        for (int j = 0; j < 2; j++) {
            const int chunk = tid + j * 256;        // 0..511
            const int kk = chunk >> 5;              // 0..15
            const int m4 = (chunk & 31) * 4;        // 0,4,..,124
            const float* srcA = AT + (size_t)(k0 + kk) * NB + m0 + m4;
            cpasync16(sAu + ((b * KTILE + kk) * SMP + m4) * 4, srcA);
            const float* srcB = BT + (size_t)(k0 + kk) * NH + n0 + m4;
            cpasync16(sBu + ((b * KTILE + kk) * SMP + m4) * 4, srcB);
        }
        asm volatile("cp.async.commit_group;\n");
    };

    stage(0, 0);

    for (int kt = 0; kt < nk; kt++) {
        const int b = kt & 1;
        __syncthreads();   // everyone done reading buffer b^1 (iter kt-1)
        if (kt + 1 < nk) {
            stage(kt + 1, b ^ 1);
            asm volatile("cp.async.wait_group 1;\n");  // tile kt arrived
        } else {
            asm volatile("cp.async.wait_group 0;\n");
        }
        __syncthreads();   // tile kt visible to all threads

        const float* sAb = sA + b * KTILE * SMP;
        const float* sBb = sB + b * KTILE * SMP;
#pragma unroll
        for (int kk = 0; kk < KTILE; kk++) {
            // A: 4 m-values (one lane-strided LDS.128), dup'd to both lanes
            float4 av = *(const float4*)(sAb + kk * SMP + lm);
            uint64_t ad0 = dup2(av.x), ad1 = dup2(av.y);
            uint64_t ad2 = dup2(av.z), ad3 = dup2(av.w);
            // B: 16 col-values = 8 packed pairs, 4 broadcast LDS.128
            const uint64_t* brow = (const uint64_t*)(sBb + kk * SMP + nw0);
#pragma unroll
            for (int q = 0; q < 4; q++) {
                ulonglong2 bp = *(const ulonglong2*)(brow + 2 * q);
                const int j0 = 2 * q;
                acc2[0][j0]     = fma2(ad0, bp.x, acc2[0][j0]);
                acc2[1][j0]     = fma2(ad1, bp.x, acc2[1][j0]);
                acc2[2][j0]     = fma2(ad2, bp.x, acc2[2][j0]);
                acc2[3][j0]     = fma2(ad3, bp.x, acc2[3][j0]);
                acc2[0][j0 + 1] = fma2(ad0, bp.y, acc2[0][j0 + 1]);
                acc2[1][j0 + 1] = fma2(ad1, bp.y, acc2[1][j0 + 1]);
                acc2[2][j0 + 1] = fma2(ad2, bp.y, acc2[2][j0 + 1]);
                acc2[3][j0 + 1] = fma2(ad3, bp.y, acc2[3][j0 + 1]);
            }
        }

        // panel boundary k=512 (kt 31): stash panel-1 sums, restart acc
        if (kt == 31) {
#pragma unroll
            for (int i = 0; i < 4; i++)
#pragma unroll
                for (int j = 0; j < 8; j++) {
                    stash[(i * 8 + j) * 256 + tid] = acc2[i][j];
                    acc2[i][j] = 0ull;
                }
        }
    }

    // ------------------------------ epilogue -------------------------------
    // 1) fold: tot = panel1 + panel2 (one rounded add, as in R9)
    uint64_t tot2[4][8];
#pragma unroll
    for (int i = 0; i < 4; i++)
#pragma unroll
        for (int j = 0; j < 8; j++)
            tot2[i][j] = add2(stash[(i * 8 + j) * 256 + tid], acc2[i][j]);
    __syncthreads();   // all folds done before stash is overwritten as tile

    // 2) stage tile to smem in (row, col) layout
#pragma unroll
    for (int i = 0; i < 4; i++) {
        const int row = lm + i;
#pragma unroll
        for (int j = 0; j < 8; j++) {
            float2 dv = unpk2(tot2[i][j]);
            *(float2*)&tile[row * TP + nw0 + 2 * j] = dv;
        }
    }
    __syncthreads();

    // 3) coalesced float4 pass: warp -> row, lane -> 4 consecutive cols
#pragma unroll
    for (int it = 0; it < 16; it++) {
        const int row = it * 8 + warp;
        const int col = lane * 4;
        float4 dv = *(const float4*)&tile[row * TP + col];
        const int c = n0 + col;
        const size_t off = (size_t)(m0 + row) * NH + c;
        float4 bias = *(const float4*)&biasA[c];
        if (MODE == 0) {
            float4 o;
            o.x = __fadd_rn(dv.x, bias.x);
            o.y = __fadd_rn(dv.y, bias.y);
            o.z = __fadd_rn(dv.z, bias.z);
            o.w = __fadd_rn(dv.w, bias.w);
            *(float4*)&outC[off] = o;
        } else {
            float4 mo = *(const float4*)&memBuf[off];
            float4 cu = *(const float4*)&curBuf[off];
            float4 nm, sp;
            {
                // reference order per element:
                //   mem = ((((0.5*mem) + cur) + d) + bias) - reset(prev)
                float v;
                v = __fadd_rn(__fmul_rn(0.5f, mo.x), cu.x);
                v = __fadd_rn(v, dv.x); v = __fadd_rn(v, bias.x);
                nm.x = __fsub_rn(v, (mo.x > 1.0f) ? 1.0f : 0.0f);
                v = __fadd_rn(__fmul_rn(0.5f, mo.y), cu.y);
                v = __fadd_rn(v, dv.y); v = __fadd_rn(v, bias.y);
                nm.y = __fsub_rn(v, (mo.y > 1.0f) ? 1.0f : 0.0f);
                v = __fadd_rn(__fmul_rn(0.5f, mo.z), cu.z);
                v = __fadd_rn(v, dv.z); v = __fadd_rn(v, bias.z);
                nm.z = __fsub_rn(v, (mo.z > 1.0f) ? 1.0f : 0.0f);
                v = __fadd_rn(__fmul_rn(0.5f, mo.w), cu.w);
                v = __fadd_rn(v, dv.w); v = __fadd_rn(v, bias.w);
                nm.w = __fsub_rn(v, (mo.w > 1.0f) ? 1.0f : 0.0f);
            }
            *(float4*)&memBuf[off] = nm;
            sp.x = (nm.x > 1.0f) ? 1.0f : 0.0f;
            sp.y = (nm.y > 1.0f) ? 1.0f : 0.0f;
            sp.z = (nm.z > 1.0f) ? 1.0f : 0.0f;
            sp.w = (nm.w > 1.0f) ? 1.0f : 0.0f;
            // overwrite tile with spikes (same thread, same address)
            *(float4*)&tile[row * TP + col] = sp;
            if (DOSUM) {
                float4 ss = *(const float4*)&ssum[off];
                ss.x = __fadd_rn(ss.x, sp.x);
                ss.y = __fadd_rn(ss.y, sp.y);
                ss.z = __fadd_rn(ss.z, sp.z);
                ss.w = __fadd_rn(ss.w, sp.w);
                *(float4*)&ssum[off] = ss;
            }
        }
    }

    // 4) MODE 1: write spikes TRANSPOSED (coalesced along batch)
    if (MODE == 1) {
        __syncthreads();
#pragma unroll
        for (int it = 0; it < 16; it++) {
            const int col = it * 8 + warp;       // feature within tile
            const int r4  = lane * 4;            // batch within tile
            float4 sp;
            sp.x = tile[(r4 + 0) * TP + col];
            sp.y = tile[(r4 + 1) * TP + col];
            sp.z = tile[(r4 + 2) * TP + col];
            sp.w = tile[(r4 + 3) * TP + col];
            *(float4*)&spkT[(size_t)(n0 + col) * NB + m0 + r4] = sp;
        }
    }
}

// ------------------------------ output kernel ------------------------------
__global__ void out_kernel(const float* __restrict__ t,
                           const float* __restrict__ W3,
                           const float* __restrict__ b3,
                           float* __restrict__ out) {
    int idx = blockIdx.x * blockDim.x + threadIdx.x;   // 0 .. NB*NO-1
    if (idx >= NB * NO) return;
    int row = idx / NO;
    int o   = idx - row * NO;
    const float* tr = t  + (size_t)row * NH;
    const float* wr = W3 + (size_t)o * NH;
    float acc = 0.f;
#pragma unroll 8
    for (int k = 0; k < NH; k++)
        acc = fmaf(__ldg(&tr[k]), __ldg(&wr[k]), acc);
    out[idx] = __fadd_rn(acc, b3[o]);
}

// ------------------------------- host launch -------------------------------
extern "C" void kernel_launch(void* const* d_in, const int* in_sizes, int n_in,
                              void* d_out, int out_size) {
    const float* x   = (const float*)d_in[0];
    const float* W1  = (const float*)d_in[1];
    const float* b1  = (const float*)d_in[2];
    const float* V1w = (const float*)d_in[3];
    const float* V1b = (const float*)d_in[4];
    const float* W2  = (const float*)d_in[5];
    const float* b2  = (const float*)d_in[6];
    const float* V2w = (const float*)d_in[7];
    const float* V2b = (const float*)d_in[8];
    const float* W3  = (const float*)d_in[9];
    const float* b3  = (const float*)d_in[10];
    float* out = (float*)d_out;

    void* p;
    float *s1aT, *s1bT, *s2aT, *s2bT, *mem1, *mem2, *cur1, *cur2, *ssum;
    float *xT, *w1T, *v1T, *w2T, *v2T;
    cudaGetSymbolAddress(&p, g_spk1aT); s1aT = (float*)p;
    cudaGetSymbolAddress(&p, g_spk1bT); s1bT = (float*)p;
    cudaGetSymbolAddress(&p, g_spk2aT); s2aT = (float*)p;
    cudaGetSymbolAddress(&p, g_spk2bT); s2bT = (float*)p;
    cudaGetSymbolAddress(&p, g_mem1);   mem1 = (float*)p;
    cudaGetSymbolAddress(&p, g_mem2);   mem2 = (float*)p;
    cudaGetSymbolAddress(&p, g_cur1);   cur1 = (float*)p;
    cudaGetSymbolAddress(&p, g_cur2);   cur2 = (float*)p;
    cudaGetSymbolAddress(&p, g_ssum);   ssum = (float*)p;
    cudaGetSymbolAddress(&p, g_xT);     xT   = (float*)p;
    cudaGetSymbolAddress(&p, g_W1T);    w1T  = (float*)p;
    cudaGetSymbolAddress(&p, g_V1T);    v1T  = (float*)p;
    cudaGetSymbolAddress(&p, g_W2T);    w2T  = (float*)p;
    cudaGetSymbolAddress(&p, g_V2T);    v2T  = (float*)p;

    cudaFuncSetAttribute(f32gemm_kernel<0, 0>,
                         cudaFuncAttributeMaxDynamicSharedMemorySize, SMEM_TOTAL);
    cudaFuncSetAttribute(f32gemm_kernel<1, 0>,
                         cudaFuncAttributeMaxDynamicSharedMemorySize, SMEM_TOTAL);
    cudaFuncSetAttribute(f32gemm_kernel<1, 1>,
                         cudaFuncAttributeMaxDynamicSharedMemorySize, SMEM_TOTAL);

    const int nElem = NB * NH;
    init_state_kernel<<<nElem / 256, 256>>>();

    // one-time transposes: x [NB][NH] -> xT [NH][NB]; W [n][k] -> WT [k][n]
    {
        dim3 tb(32, 8);
        transpose_kernel<<<dim3(NH / 32, NB / 32), tb>>>(x, xT, NB, NH);
        transpose_kernel<<<dim3(NH / 32, NH / 32), tb>>>(W1,  w1T, NH, NH);
        transpose_kernel<<<dim3(NH / 32, NH / 32), tb>>>(V1w, v1T, NH, NH);
        transpose_kernel<<<dim3(NH / 32, NH / 32), tb>>>(W2,  w2T, NH, NH);
        transpose_kernel<<<dim3(NH / 32, NH / 32), tb>>>(V2w, v2T, NH, NH);
    }

    dim3 grid(NH / 128, NB / 128);   // (8, 128)
    dim3 block(256);

    // cur1 = x @ W1^T + b1
    f32gemm_kernel<0, 0><<<grid, block, SMEM_TOTAL>>>(
        xT, w1T, b1, nullptr, nullptr, nullptr, nullptr, cur1);

    for (int st = 0; st < NSTEPS; st++) {
        const float* s1in = (st & 1) ? s1bT : s1aT;
        float*      s1out = (st & 1) ? s1aT : s1bT;
        const float* s2in = (st & 1) ? s2bT : s2aT;
        float*      s2out = (st & 1) ? s2aT : s2bT;

        // layer 1: mem1 = 0.5*mem1 + cur1 + s1in@V1w^T + V1b - reset; spike
        f32gemm_kernel<1, 0><<<grid, block, SMEM_TOTAL>>>(
            s1in, v1T, V1b, mem1, cur1, s1out, nullptr, nullptr);

        // cur2 = s1out @ W2^T + b2  (separately rounded)
        f32gemm_kernel<0, 0><<<grid, block, SMEM_TOTAL>>>(
            s1out, w2T, b2, nullptr, nullptr, nullptr, nullptr, cur2);

        // layer 2: mem2 = 0.5*mem2 + cur2 + s2in@V2w^T + V2b - reset;
        //          spike; ssum += spike
        f32gemm_kernel<1, 1><<<grid, block, SMEM_TOTAL>>>(
            s2in, v2T, V2b, mem2, cur2, s2out, ssum, nullptr);
    }

    // t = ssum/25 (rounded first), then out = t@W3^T + b3
    div25_kernel<<<nElem / 256, 256>>>(ssum);
    out_kernel<<<(NB * NO + 255) / 256, 256>>>(ssum, W3, b3, out);
}

// round 16
// speedup vs baseline: 2.2718x; 1.0621x over previous
#include <cuda_runtime.h>
#include <cstdint>
#include <cstddef>

// ---------------------------------------------------------------------------
// SNN, fp32-faithful, PASSING association (round 9): per output, fp32 FMA
// chain ascending k; K panels [0,512),[512,1024); panel sums combined with
// one rounded add. Schedule-only changes this round:
//  * single-barrier cp.async pipeline: stage(kt+1) AFTER the barrier makes
//    the 2-stage buffer race-free with ONE __syncthreads per k-tile
//    (R15 had two -> barrier overhead halved)
//  * SMP 132 -> 128 (padding only needed for the old strided STS path)
//  * everything else identical to R15 (k-major operands via one-time
//    transposes, spikes written transposed, stash + coalesced epilogue)
// ---------------------------------------------------------------------------

#define NB 16384
#define NH 1024
#define NSTEPS 25
#define NO 10

#define KTILE 16
#define SMP 128        // smem row pitch (floats)
#define TP  132        // epilogue tile pitch (floats)
#define SA_BYTES  (2 * KTILE * SMP * 4)            // 16KB
#define SB_BYTES  (2 * KTILE * SMP * 4)            // 16KB
#define STASH_BYTES (128 * TP * 4)                 // 67.6KB >= 64KB u64 stash
#define SMEM_TOTAL (SA_BYTES + SB_BYTES + STASH_BYTES)   // ~98KB

// ----------------------------- device scratch ------------------------------
// transposed spike buffers: [feature][batch]
__device__ __align__(16) float g_spk1aT[NH * NB];
__device__ __align__(16) float g_spk1bT[NH * NB];
__device__ __align__(16) float g_spk2aT[NH * NB];
__device__ __align__(16) float g_spk2bT[NH * NB];
__device__ __align__(16) float g_mem1[NB * NH];
__device__ __align__(16) float g_mem2[NB * NH];
__device__ __align__(16) float g_cur1[NB * NH];
__device__ __align__(16) float g_cur2[NB * NH];
__device__ __align__(16) float g_ssum[NB * NH];
__device__ __align__(16) float g_xT [NH * NB];    // x transposed
__device__ __align__(16) float g_W1T[NH * NH];    // weights [k][n]
__device__ __align__(16) float g_V1T[NH * NH];
__device__ __align__(16) float g_W2T[NH * NH];
__device__ __align__(16) float g_V2T[NH * NH];

// --------------------------- f32x2 packed helpers ---------------------------
__device__ __forceinline__ uint64_t dup2(float x) {
    uint64_t d;
    asm("mov.b64 %0, {%1, %2};" : "=l"(d) : "f"(x), "f"(x));
    return d;
}
__device__ __forceinline__ uint64_t fma2(uint64_t a, uint64_t b, uint64_t c) {
    uint64_t d;
    asm("fma.rn.f32x2 %0, %1, %2, %3;" : "=l"(d) : "l"(a), "l"(b), "l"(c));
    return d;
}
__device__ __forceinline__ uint64_t add2(uint64_t a, uint64_t b) {
    uint64_t d;
    asm("add.rn.f32x2 %0, %1, %2;" : "=l"(d) : "l"(a), "l"(b));
    return d;
}
__device__ __forceinline__ float2 unpk2(uint64_t v) {
    float lo, hi;
    asm("mov.b64 {%0, %1}, %2;" : "=f"(lo), "=f"(hi) : "l"(v));
    return make_float2(lo, hi);
}
__device__ __forceinline__ uint32_t smem_u32(const void* p) {
    return (uint32_t)__cvta_generic_to_shared(p);
}
__device__ __forceinline__ void cpasync16(uint32_t dst, const void* src) {
    asm volatile("cp.async.cg.shared.global [%0], [%1], 16;\n"
                 :: "r"(dst), "l"(src));
}

// ------------------------------- prep kernels ------------------------------
__global__ void init_state_kernel() {
    size_t i = (size_t)blockIdx.x * blockDim.x + threadIdx.x;
    g_mem1[i] = 0.f;
    g_mem2[i] = 0.f;
    g_ssum[i] = 0.f;
    g_spk1aT[i] = 0.f;
    g_spk2aT[i] = 0.f;
}

__global__ void div25_kernel(float* __restrict__ s) {
    size_t i = (size_t)blockIdx.x * blockDim.x + threadIdx.x;
    s[i] = __fdiv_rn(s[i], 25.0f);
}

// tiled transpose: in [R][C] -> out [C][R]; R, C multiples of 32
__global__ void transpose_kernel(const float* __restrict__ in,
                                 float* __restrict__ out, int R, int C) {
    __shared__ float t[32][33];
    const int c0 = blockIdx.x * 32;
    const int r0 = blockIdx.y * 32;
    const int tx = threadIdx.x;      // 0..31
    const int ty = threadIdx.y;      // 0..7
#pragma unroll
    for (int i = 0; i < 4; i++)
        t[ty + 8 * i][tx] = in[(size_t)(r0 + ty + 8 * i) * C + c0 + tx];
    __syncthreads();
#pragma unroll
    for (int i = 0; i < 4; i++)
        out[(size_t)(c0 + ty + 8 * i) * R + r0 + tx] = t[tx][ty + 8 * i];
}

// ------------------------------- GEMM kernel -------------------------------
// C[m,n] = sum_k AT[k,m]*BT[k,n]: panels [0,512),[512,1024), serial ascending
// k within panel, one rounded add to combine (EXACTLY as passing R9).
// 256 threads, tile 128x128: warp w -> cols [w*16, w*16+16);
// lane -> rows [lane*4, lane*4+4). Both operands cp.async'd (k-major).

// MODE 0: outC = tot + biasA[n]
// MODE 1: mem = 0.5*mem + cur + tot + biasA - reset; spike -> spkT; [DOSUM]
template <int MODE, int DOSUM>
__global__ void __launch_bounds__(256, 2)
f32gemm_kernel(const float* __restrict__ AT, const float* __restrict__ BT,
               const float* __restrict__ biasA,
               float* __restrict__ memBuf, const float* __restrict__ curBuf,
               float* __restrict__ spkT,
               float* __restrict__ ssum, float* __restrict__ outC) {
    extern __shared__ __align__(16) char dsmem[];
    float* sA = (float*)dsmem;                     // [2][KTILE][SMP]
    float* sB = (float*)(dsmem + SA_BYTES);        // [2][KTILE][SMP]
    char*  stashc = dsmem + SA_BYTES + SB_BYTES;
    uint64_t* stash = (uint64_t*)stashc;           // [32][256] during mainloop
    float* tile = (float*)stashc;                  // [128][TP] in epilogue

    const uint32_t sAu = smem_u32(sA);
    const uint32_t sBu = smem_u32(sB);

    const int tid  = threadIdx.x;
    const int warp = tid >> 5;       // 0..7
    const int lane = tid & 31;
    const int nw0  = warp * 16;      // col block for this warp
    const int lm   = lane * 4;       // row block for this lane
    const int m0   = blockIdx.y * 128;
    const int n0   = blockIdx.x * 128;

    uint64_t acc2[4][8];
#pragma unroll
    for (int i = 0; i < 4; i++)
#pragma unroll
        for (int j = 0; j < 8; j++) acc2[i][j] = 0ull;

    const int nk = NH / KTILE;   // 64

    // cp.async staging: 2 A chunks + 2 B chunks (16B each) per thread/ktile
    auto stage = [&](int kt, int b) {
        const int k0 = kt * KTILE;
#pragma unroll
        for (int j = 0; j < 2; j++) {
            const int chunk = tid + j * 256;        // 0..511
            const int kk = chunk >> 5;              // 0..15
            const int m4 = (chunk & 31) * 4;        // 0,4,..,124
            const float* srcA = AT + (size_t)(k0 + kk) * NB + m0 + m4;
            cpasync16(sAu + ((b * KTILE + kk) * SMP + m4) * 4, srcA);
            const float* srcB = BT + (size_t)(k0 + kk) * NH + n0 + m4;
            cpasync16(sBu + ((b * KTILE + kk) * SMP + m4) * 4, srcB);
        }
        asm volatile("cp.async.commit_group;\n");
    };

    stage(0, 0);

    for (int kt = 0; kt < nk; kt++) {
        const int b = kt & 1;
        // tile kt arrived (issued last iteration); barrier also guarantees
        // every warp finished computing tile kt-1 (buffer b^1), so staging
        // into b^1 AFTER the barrier is race-free -> one barrier per k-tile.
        asm volatile("cp.async.wait_group 0;\n");
        __syncthreads();
        if (kt + 1 < nk) stage(kt + 1, b ^ 1);

        const float* sAb = sA + b * KTILE * SMP;
        const float* sBb = sB + b * KTILE * SMP;
#pragma unroll
        for (int kk = 0; kk < KTILE; kk++) {
            // A: 4 m-values (one lane-strided LDS.128), dup'd to both lanes
            float4 av = *(const float4*)(sAb + kk * SMP + lm);
            uint64_t ad0 = dup2(av.x), ad1 = dup2(av.y);
            uint64_t ad2 = dup2(av.z), ad3 = dup2(av.w);
            // B: 16 col-values = 8 packed pairs, 4 broadcast LDS.128
            const uint64_t* brow = (const uint64_t*)(sBb + kk * SMP + nw0);
#pragma unroll
            for (int q = 0; q < 4; q++) {
                ulonglong2 bp = *(const ulonglong2*)(brow + 2 * q);
                const int j0 = 2 * q;
                acc2[0][j0]     = fma2(ad0, bp.x, acc2[0][j0]);
                acc2[1][j0]     = fma2(ad1, bp.x, acc2[1][j0]);
                acc2[2][j0]     = fma2(ad2, bp.x, acc2[2][j0]);
                acc2[3][j0]     = fma2(ad3, bp.x, acc2[3][j0]);
                acc2[0][j0 + 1] = fma2(ad0, bp.y, acc2[0][j0 + 1]);
                acc2[1][j0 + 1] = fma2(ad1, bp.y, acc2[1][j0 + 1]);
                acc2[2][j0 + 1] = fma2(ad2, bp.y, acc2[2][j0 + 1]);
                acc2[3][j0 + 1] = fma2(ad3, bp.y, acc2[3][j0 + 1]);
            }
        }

        // panel boundary k=512 (kt 31): stash panel-1 sums, restart acc
        if (kt == 31) {
#pragma unroll
            for (int i = 0; i < 4; i++)
#pragma unroll
                for (int j = 0; j < 8; j++) {
                    stash[(i * 8 + j) * 256 + tid] = acc2[i][j];
                    acc2[i][j] = 0ull;
                }
        }
    }

    // ------------------------------ epilogue -------------------------------
    // 1) fold: tot = panel1 + panel2 (one rounded add, as in R9)
    uint64_t tot2[4][8];
#pragma unroll
    for (int i = 0; i < 4; i++)
#pragma unroll
        for (int j = 0; j < 8; j++)
            tot2[i][j] = add2(stash[(i * 8 + j) * 256 + tid], acc2[i][j]);
    __syncthreads();   // all folds done before stash is overwritten as tile

    // 2) stage tile to smem in (row, col) layout
#pragma unroll
    for (int i = 0; i < 4; i++) {
        const int row = lm + i;
#pragma unroll
        for (int j = 0; j < 8; j++) {
            float2 dv = unpk2(tot2[i][j]);
            *(float2*)&tile[row * TP + nw0 + 2 * j] = dv;
        }
    }
    __syncthreads();

    // 3) coalesced float4 pass: warp -> row, lane -> 4 consecutive cols
#pragma unroll
    for (int it = 0; it < 16; it++) {
        const int row = it * 8 + warp;
        const int col = lane * 4;
        float4 dv = *(const float4*)&tile[row * TP + col];
        const int c = n0 + col;
        const size_t off = (size_t)(m0 + row) * NH + c;
        float4 bias = *(const float4*)&biasA[c];
        if (MODE == 0) {
            float4 o;
            o.x = __fadd_rn(dv.x, bias.x);
            o.y = __fadd_rn(dv.y, bias.y);
            o.z = __fadd_rn(dv.z, bias.z);
            o.w = __fadd_rn(dv.w, bias.w);
            *(float4*)&outC[off] = o;
        } else {
            float4 mo = *(const float4*)&memBuf[off];
            float4 cu = *(const float4*)&curBuf[off];
            float4 nm, sp;
            {
                // reference order per element:
                //   mem = ((((0.5*mem) + cur) + d) + bias) - reset(prev)
                float v;
                v = __fadd_rn(__fmul_rn(0.5f, mo.x), cu.x);
                v = __fadd_rn(v, dv.x); v = __fadd_rn(v, bias.x);
                nm.x = __fsub_rn(v, (mo.x > 1.0f) ? 1.0f : 0.0f);
                v = __fadd_rn(__fmul_rn(0.5f, mo.y), cu.y);
                v = __fadd_rn(v, dv.y); v = __fadd_rn(v, bias.y);
                nm.y = __fsub_rn(v, (mo.y > 1.0f) ? 1.0f : 0.0f);
                v = __fadd_rn(__fmul_rn(0.5f, mo.z), cu.z);
                v = __fadd_rn(v, dv.z); v = __fadd_rn(v, bias.z);
                nm.z = __fsub_rn(v, (mo.z > 1.0f) ? 1.0f : 0.0f);
                v = __fadd_rn(__fmul_rn(0.5f, mo.w), cu.w);
                v = __fadd_rn(v, dv.w); v = __fadd_rn(v, bias.w);
                nm.w = __fsub_rn(v, (mo.w > 1.0f) ? 1.0f : 0.0f);
            }
            *(float4*)&memBuf[off] = nm;
            sp.x = (nm.x > 1.0f) ? 1.0f : 0.0f;
            sp.y = (nm.y > 1.0f) ? 1.0f : 0.0f;
            sp.z = (nm.z > 1.0f) ? 1.0f : 0.0f;
            sp.w = (nm.w > 1.0f) ? 1.0f : 0.0f;
            // overwrite tile with spikes (same thread, same address)
            *(float4*)&tile[row * TP + col] = sp;
            if (DOSUM) {
                float4 ss = *(const float4*)&ssum[off];
                ss.x = __fadd_rn(ss.x, sp.x);
                ss.y = __fadd_rn(ss.y, sp.y);
                ss.z = __fadd_rn(ss.z, sp.z);
                ss.w = __fadd_rn(ss.w, sp.w);
                *(float4*)&ssum[off] = ss;
            }
        }
    }

    // 4) MODE 1: write spikes TRANSPOSED (coalesced along batch)
    if (MODE == 1) {
        __syncthreads();
#pragma unroll
        for (int it = 0; it < 16; it++) {
            const int col = it * 8 + warp;       // feature within tile
            const int r4  = lane * 4;            // batch within tile
            float4 sp;
            sp.x = tile[(r4 + 0) * TP + col];
            sp.y = tile[(r4 + 1) * TP + col];
            sp.z = tile[(r4 + 2) * TP + col];
            sp.w = tile[(r4 + 3) * TP + col];
            *(float4*)&spkT[(size_t)(n0 + col) * NB + m0 + r4] = sp;
        }
    }
}

// ------------------------------ output kernel ------------------------------
__global__ void out_kernel(const float* __restrict__ t,
                           const float* __restrict__ W3,
                           const float* __restrict__ b3,
                           float* __restrict__ out) {
    int idx = blockIdx.x * blockDim.x + threadIdx.x;   // 0 .. NB*NO-1
    if (idx >= NB * NO) return;
    int row = idx / NO;
    int o   = idx - row * NO;
    const float* tr = t  + (size_t)row * NH;
    const float* wr = W3 + (size_t)o * NH;
    float acc = 0.f;
#pragma unroll 8
    for (int k = 0; k < NH; k++)
        acc = fmaf(__ldg(&tr[k]), __ldg(&wr[k]), acc);
    out[idx] = __fadd_rn(acc, b3[o]);
}

// ------------------------------- host launch -------------------------------
extern "C" void kernel_launch(void* const* d_in, const int* in_sizes, int n_in,
                              void* d_out, int out_size) {
    const float* x   = (const float*)d_in[0];
    const float* W1  = (const float*)d_in[1];
    const float* b1  = (const float*)d_in[2];
    const float* V1w = (const float*)d_in[3];
    const float* V1b = (const float*)d_in[4];
    const float* W2  = (const float*)d_in[5];
    const float* b2  = (const float*)d_in[6];
    const float* V2w = (const float*)d_in[7];
    const float* V2b = (const float*)d_in[8];
    const float* W3  = (const float*)d_in[9];
    const float* b3  = (const float*)d_in[10];
    float* out = (float*)d_out;

    void* p;
    float *s1aT, *s1bT, *s2aT, *s2bT, *mem1, *mem2, *cur1, *cur2, *ssum;
    float *xT, *w1T, *v1T, *w2T, *v2T;
    cudaGetSymbolAddress(&p, g_spk1aT); s1aT = (float*)p;
    cudaGetSymbolAddress(&p, g_spk1bT); s1bT = (float*)p;
    cudaGetSymbolAddress(&p, g_spk2aT); s2aT = (float*)p;
    cudaGetSymbolAddress(&p, g_spk2bT); s2bT = (float*)p;
    cudaGetSymbolAddress(&p, g_mem1);   mem1 = (float*)p;
    cudaGetSymbolAddress(&p, g_mem2);   mem2 = (float*)p;
    cudaGetSymbolAddress(&p, g_cur1);   cur1 = (float*)p;
    cudaGetSymbolAddress(&p, g_cur2);   cur2 = (float*)p;
    cudaGetSymbolAddress(&p, g_ssum);   ssum = (float*)p;
    cudaGetSymbolAddress(&p, g_xT);     xT   = (float*)p;
    cudaGetSymbolAddress(&p, g_W1T);    w1T  = (float*)p;
    cudaGetSymbolAddress(&p, g_V1T);    v1T  = (float*)p;
    cudaGetSymbolAddress(&p, g_W2T);    w2T  = (float*)p;
    cudaGetSymbolAddress(&p, g_V2T);    v2T  = (float*)p;

    cudaFuncSetAttribute(f32gemm_kernel<0, 0>,
                         cudaFuncAttributeMaxDynamicSharedMemorySize, SMEM_TOTAL);
    cudaFuncSetAttribute(f32gemm_kernel<1, 0>,
                         cudaFuncAttributeMaxDynamicSharedMemorySize, SMEM_TOTAL);
    cudaFuncSetAttribute(f32gemm_kernel<1, 1>,
                         cudaFuncAttributeMaxDynamicSharedMemorySize, SMEM_TOTAL);

    const int nElem = NB * NH;
    init_state_kernel<<<nElem / 256, 256>>>();

    // one-time transposes: x [NB][NH] -> xT [NH][NB]; W [n][k] -> WT [k][n]
    {
        dim3 tb(32, 8);
        transpose_kernel<<<dim3(NH / 32, NB / 32), tb>>>(x, xT, NB, NH);
        transpose_kernel<<<dim3(NH / 32, NH / 32), tb>>>(W1,  w1T, NH, NH);
        transpose_kernel<<<dim3(NH / 32, NH / 32), tb>>>(V1w, v1T, NH, NH);
        transpose_kernel<<<dim3(NH / 32, NH / 32), tb>>>(W2,  w2T, NH, NH);
        transpose_kernel<<<dim3(NH / 32, NH / 32), tb>>>(V2w, v2T, NH, NH);
    }

    dim3 grid(NH / 128, NB / 128);   // (8, 128)
    dim3 block(256);

    // cur1 = x @ W1^T + b1
    f32gemm_kernel<0, 0><<<grid, block, SMEM_TOTAL>>>(
        xT, w1T, b1, nullptr, nullptr, nullptr, nullptr, cur1);

    for (int st = 0; st < NSTEPS; st++) {
        const float* s1in = (st & 1) ? s1bT : s1aT;
        float*      s1out = (st & 1) ? s1aT : s1bT;
        const float* s2in = (st & 1) ? s2bT : s2aT;
        float*      s2out = (st & 1) ? s2aT : s2bT;

        // layer 1: mem1 = 0.5*mem1 + cur1 + s1in@V1w^T + V1b - reset; spike
        f32gemm_kernel<1, 0><<<grid, block, SMEM_TOTAL>>>(
            s1in, v1T, V1b, mem1, cur1, s1out, nullptr, nullptr);

        // cur2 = s1out @ W2^T + b2  (separately rounded)
        f32gemm_kernel<0, 0><<<grid, block, SMEM_TOTAL>>>(
            s1out, w2T, b2, nullptr, nullptr, nullptr, nullptr, cur2);

        // layer 2: mem2 = 0.5*mem2 + cur2 + s2in@V2w^T + V2b - reset;
        //          spike; ssum += spike
        f32gemm_kernel<1, 1><<<grid, block, SMEM_TOTAL>>>(
            s2in, v2T, V2b, mem2, cur2, s2out, ssum, nullptr);
    }

    // t = ssum/25 (rounded first), then out = t@W3^T + b3
    div25_kernel<<<nElem / 256, 256>>>(ssum);
    out_kernel<<<(NB * NO + 255) / 256, 256>>>(ssum, W3, b3, out);
}